// round 7
// baseline (speedup 1.0000x reference)
#include <cuda_runtime.h>
#include <cuda_fp16.h>
#include <stdint.h>

#define Bb 4
#define Ss 4096
#define Dd 1024
#define MTOT (Bb * Ss)   // 16384

// ---------------------------------------------------------------------------
// Scratch (device globals; allocation is forbidden)
// ---------------------------------------------------------------------------
__device__ __half g_i16 [(size_t)MTOT * Dd];        // inputs fp16
__device__ __half g_c16 [(size_t)MTOT * Dd];        // context fp16
__device__ __half g_q16 [(size_t)MTOT * Dd];        // q_phi fp16
__device__ __half g_kT16[(size_t)Bb * Dd * Ss];     // k_phi^T [b,d,s]
__device__ __half g_vT16[(size_t)Bb * Dd * Ss];     // v^T     [b,e,s]
__device__ __half g_at16[(size_t)MTOT * Dd];        // att * 1024
__device__ __half g_kvT16[(size_t)Bb * Dd * Dd];    // kv^T    [b,e,d]
__device__ __half g_Wt16[(size_t)4 * Dd * Dd];      // W^T (q,k,v,o)
__device__ float  g_ksum[Bb * Dd];
__device__ float  g_z  [Bb * Ss];

#define ATT_SCALE    1024.0f
#define ATT_INVSCALE (1.0f / 1024.0f)

// ---------------------------------------------------------------------------
// Helpers (baseline compute_103: mma.sync / ldmatrix / cp.async only)
// ---------------------------------------------------------------------------
static __device__ __forceinline__ uint32_t smem_u32(const void* p) {
    uint32_t a;
    asm("{ .reg .u64 t; cvta.to.shared.u64 t, %1; cvt.u32.u64 %0, t; }"
        : "=r"(a) : "l"(p));
    return a;
}

static __device__ __forceinline__ void ldsm4(uint32_t* r, uint32_t addr) {
    asm volatile("ldmatrix.sync.aligned.m8n8.x4.shared.b16 {%0,%1,%2,%3}, [%4];"
                 : "=r"(r[0]), "=r"(r[1]), "=r"(r[2]), "=r"(r[3]) : "r"(addr));
}

static __device__ __forceinline__ void mma16816(float* d, const uint32_t* a,
                                                const uint32_t* b) {
    asm volatile(
        "mma.sync.aligned.m16n8k16.row.col.f32.f16.f16.f32 "
        "{%0,%1,%2,%3}, {%4,%5,%6,%7}, {%8,%9}, {%0,%1,%2,%3};"
        : "+f"(d[0]), "+f"(d[1]), "+f"(d[2]), "+f"(d[3])
        : "r"(a[0]), "r"(a[1]), "r"(a[2]), "r"(a[3]), "r"(b[0]), "r"(b[1]));
}

#define CP16(dst, src) \
    asm volatile("cp.async.cg.shared.global [%0], [%1], 16;" :: "r"(dst), "l"(src))
#define CP_COMMIT() asm volatile("cp.async.commit_group;" ::: "memory")
#define CP_WAIT1()  asm volatile("cp.async.wait_group 1;" ::: "memory")

static __device__ __forceinline__ uint32_t pack2h(__half a, __half b) {
    return (uint32_t)__half_as_ushort(a) | ((uint32_t)__half_as_ushort(b) << 16);
}

// ---------------------------------------------------------------------------
// fp16 warp-MMA GEMM: C[128x256 CTA tile] = A @ B^T  (fp32 accumulate)
//   A: [M,K] K-major fp16; B: [N,K] K-major fp16.
//   CTA 128x256, K-chunk 64, 8 warps (2M x 4N), warp tile 64x64.
//   3-stage cp.async pipeline (48KB/stage), xor-swizzled 128B rows.
//   256 threads/CTA, 1 CTA/SM, 8 warps/SM.
// ---------------------------------------------------------------------------
enum { E_Q = 0, E_K = 1, E_V = 2, E_KVP = 3, E_ATT = 4, E_OUT = 5 };

#define A_BYTES  16384            // 128 rows x 128B
#define B_BYTES  32768            // 256 rows x 128B
#define STAGE_B  (A_BYTES + B_BYTES)   // 49152
#define SMEM_DYN (3 * STAGE_B)         // 147456

template<int EPI>
__global__ __launch_bounds__(256, 1)
void mma_gemm(const __half* __restrict__ Ag, const __half* __restrict__ Bg,
              int K, int lda, int ldb, long long sA, long long sB,
              const float* __restrict__ bias, const float* __restrict__ zarr,
              const float* __restrict__ resid, float* __restrict__ Cf,
              __half* __restrict__ Ch)
{
    extern __shared__ __align__(1024) char dsm[];
    const uint32_t sbase = smem_u32(dsm);

    const int tid  = threadIdx.x;
    const int w    = tid >> 5, lane = tid & 31;
    const int wm0  = (w >> 2) * 64;     // 2 M-warps
    const int wn0  = (w & 3) * 64;      // 4 N-warps
    const int bz    = blockIdx.z;
    const int rbase = blockIdx.y * 128;
    const int cbase = blockIdx.x * 256;

    const __half* pA = Ag + (size_t)bz * sA;
    const __half* pB = Bg + (size_t)bz * sB;

    float acc[4][8][4];
    #pragma unroll
    for (int a = 0; a < 4; a++)
        #pragma unroll
        for (int b = 0; b < 8; b++)
            #pragma unroll
            for (int c = 0; c < 4; c++) acc[a][b][c] = 0.f;

    // ---- stage loader: A 128x128B + B 256x128B, xor-8 swizzle, 256 thr ----
    auto load_stage = [&](int stg, int it) {
        const uint32_t sb = sbase + stg * STAGE_B;
        const size_t k0 = (size_t)it * 64;
        const int u = tid & 7;
        #pragma unroll
        for (int i = 0; i < 4; i++) {
            const int row = (tid >> 3) + i * 32;
            const uint32_t off = ((uint32_t)row << 7) + (uint32_t)((u ^ (row & 7)) << 4);
            CP16(sb + off, pA + (size_t)(rbase + row) * lda + k0 + (size_t)u * 8);
        }
        #pragma unroll
        for (int i = 0; i < 8; i++) {
            const int row = (tid >> 3) + i * 32;
            const uint32_t off = ((uint32_t)row << 7) + (uint32_t)((u ^ (row & 7)) << 4);
            CP16(sb + A_BYTES + off, pB + (size_t)(cbase + row) * ldb + k0 + (size_t)u * 8);
        }
    };

    const int nch = K >> 6;
    load_stage(0, 0); CP_COMMIT();
    load_stage(1, 1); CP_COMMIT();

    const int la15 = lane & 15, la7 = lane & 7;
    const uint32_t aRowB = (uint32_t)(wm0 + la15) << 7;
    const int aSel = lane >> 4;
    const int bRow = wn0 + la7 + ((lane >> 1) & 8);
    const int bSel = (lane >> 3) & 1;

    for (int it = 0; it < nch; ++it) {
        CP_WAIT1();
        __syncthreads();
        if (it + 2 < nch) load_stage((it + 2) % 3, it + 2);
        CP_COMMIT();

        const uint32_t sb = sbase + (it % 3) * STAGE_B;
        #pragma unroll
        for (int ks = 0; ks < 4; ++ks) {
            uint32_t ah[4][4], bh[4][4];
            #pragma unroll
            for (int mt = 0; mt < 4; mt++) {
                const uint32_t ad = sb + aRowB + (mt << 11)
                                  + (uint32_t)((((ks << 1) + aSel) ^ la7) << 4);
                ldsm4(ah[mt], ad);
            }
            #pragma unroll
            for (int nt = 0; nt < 4; nt++) {
                const uint32_t bd = sb + A_BYTES
                                  + ((uint32_t)(bRow + (nt << 4)) << 7)
                                  + (uint32_t)((((ks << 1) + bSel) ^ la7) << 4);
                ldsm4(bh[nt], bd);
            }
            #pragma unroll
            for (int mt = 0; mt < 4; mt++)
                #pragma unroll
                for (int nt = 0; nt < 4; nt++)
                    #pragma unroll
                    for (int s2 = 0; s2 < 2; s2++)
                        mma16816(acc[mt][nt * 2 + s2], ah[mt], &bh[nt][s2 * 2]);
        }
    }

    // ------------------------------ epilogue -------------------------------
    const int rQ = lane >> 2;          // 0..7
    const int cP = (lane & 3) * 2;     // 0,2,4,6

    if (EPI == E_Q || EPI == E_ATT || EPI == E_OUT) {
        #pragma unroll
        for (int mt = 0; mt < 4; mt++)
            #pragma unroll
            for (int h = 0; h < 2; h++) {
                const int grow = rbase + wm0 + mt * 16 + rQ + h * 8;
                float zv = 1.f;
                if (EPI == E_ATT) zv = zarr[(size_t)bz * Ss + grow] * ATT_SCALE;
                #pragma unroll
                for (int nt8 = 0; nt8 < 8; nt8++) {
                    const int gcol = cbase + wn0 + nt8 * 8 + cP;
                    float v0 = acc[mt][nt8][h * 2 + 0];
                    float v1 = acc[mt][nt8][h * 2 + 1];
                    if (EPI == E_OUT) { v0 *= ATT_INVSCALE; v1 *= ATT_INVSCALE; }
                    if (EPI == E_Q || EPI == E_OUT) {
                        v0 += bias[gcol];
                        v1 += bias[gcol + 1];
                    }
                    if (EPI == E_Q) {
                        v0 = (v0 > 0.f) ? (v0 + 1.f) : __expf(v0);
                        v1 = (v1 > 0.f) ? (v1 + 1.f) : __expf(v1);
                    }
                    if (EPI == E_ATT) { v0 *= zv; v1 *= zv; }
                    if (EPI == E_OUT) {
                        const size_t gi = (size_t)grow * Dd + gcol;
                        float2 rv = *(const float2*)(resid + gi);
                        *(float2*)(Cf + gi) = make_float2(v0 + rv.x, v1 + rv.y);
                    } else {
                        const size_t gi = (EPI == E_Q)
                            ? (size_t)grow * Dd + gcol
                            : ((size_t)bz * Ss + grow) * (size_t)Dd + gcol;
                        *(uint32_t*)(Ch + gi) =
                            pack2h(__float2half_rn(v0), __float2half_rn(v1));
                    }
                }
            }
    } else {
        // E_K / E_V / E_KVP: transpose via smem staging, coalesced stores
        __syncthreads();                      // compute done; reuse dsm
        __half* sT = (__half*)dsm;            // 256 cols x 136 rows fp16
        #pragma unroll
        for (int mt = 0; mt < 4; mt++)
            #pragma unroll
            for (int h = 0; h < 2; h++) {
                const int r = wm0 + mt * 16 + rQ + h * 8;
                #pragma unroll
                for (int nt8 = 0; nt8 < 8; nt8++) {
                    const int c = wn0 + nt8 * 8 + cP;
                    float v0 = acc[mt][nt8][h * 2 + 0];
                    float v1 = acc[mt][nt8][h * 2 + 1];
                    if (EPI == E_K || EPI == E_V) {
                        v0 += bias[cbase + c];
                        v1 += bias[cbase + c + 1];
                    }
                    if (EPI == E_K) {
                        v0 = (v0 > 0.f) ? (v0 + 1.f) : __expf(v0);
                        v1 = (v1 > 0.f) ? (v1 + 1.f) : __expf(v1);
                    }
                    sT[c * 136 + r]       = __float2half_rn(v0);
                    sT[(c + 1) * 136 + r] = __float2half_rn(v1);
                }
            }
        __syncthreads();
        const int bGl = rbase >> 12;
        const int s0  = rbase & (Ss - 1);
        #pragma unroll
        for (int i = 0; i < 16; i++) {
            const int e  = i * 256 + tid;       // 0..4095
            const int c  = e >> 4;              // 0..255
            const int ru = e & 15;
            uint4 hv = *(const uint4*)(sT + c * 136 + ru * 8);
            size_t gi;
            if (EPI == E_KVP)
                gi = ((size_t)bz * Dd + cbase + c) * (size_t)Dd + rbase + ru * 8;
            else
                gi = ((size_t)bGl * Dd + cbase + c) * (size_t)Ss + s0 + ru * 8;
            *(uint4*)(Ch + gi) = hv;
        }
    }
}

// ---------------------------------------------------------------------------
// fp32 -> fp16 convert (8 elems/thread)
// ---------------------------------------------------------------------------
__global__ void tofp16_k(const float* __restrict__ x, __half* __restrict__ h)
{
    const size_t i = ((size_t)blockIdx.x * 256 + threadIdx.x) * 8;
    float4 a = *(const float4*)(x + i);
    float4 b = *(const float4*)(x + i + 4);
    uint4 o;
    o.x = pack2h(__float2half_rn(a.x), __float2half_rn(a.y));
    o.y = pack2h(__float2half_rn(a.z), __float2half_rn(a.w));
    o.z = pack2h(__float2half_rn(b.x), __float2half_rn(b.y));
    o.w = pack2h(__float2half_rn(b.z), __float2half_rn(b.w));
    *(uint4*)(h + i) = o;
}

// ---------------------------------------------------------------------------
// W [K,N] -> Wt [N,K] fp16 (smem tile transpose)
// ---------------------------------------------------------------------------
__global__ void wsplit_k(const float* __restrict__ Wq, const float* __restrict__ Wk,
                         const float* __restrict__ Wv, const float* __restrict__ Wo)
{
    __shared__ float t[32][33];
    const float* W = (blockIdx.z == 0) ? Wq : (blockIdx.z == 1) ? Wk
                   : (blockIdx.z == 2) ? Wv : Wo;
    __half* Th = g_Wt16 + (size_t)blockIdx.z * Dd * Dd;
    const int n0 = blockIdx.x * 32, k0 = blockIdx.y * 32;
    const int tx = threadIdx.x, ty = threadIdx.y;
    #pragma unroll
    for (int i = 0; i < 4; i++)
        t[ty + i * 8][tx] = W[(size_t)(k0 + ty + i * 8) * Dd + n0 + tx];
    __syncthreads();
    #pragma unroll
    for (int i = 0; i < 4; i++) {
        const int r = ty + i * 8;
        Th[(size_t)(n0 + r) * Dd + k0 + tx] = __float2half_rn(t[tx][r]);
    }
}

// ---------------------------------------------------------------------------
// k_sum[b,d] = sum_s k_phi^T[b,d,s]  (one warp per contiguous row)
// ---------------------------------------------------------------------------
__global__ void ksum_k()
{
    const int gw = (blockIdx.x * blockDim.x + threadIdx.x) >> 5;  // 0..4095
    const int lane = threadIdx.x & 31;
    const uint4* ph = (const uint4*)(g_kT16 + (size_t)gw * Ss);
    float s = 0.f;
    #pragma unroll 4
    for (int i = 0; i < 16; i++) {
        uint4 xh = ph[i * 32 + lane];
        const __half2* h2 = (const __half2*)&xh;
        #pragma unroll
        for (int t = 0; t < 4; t++) {
            float2 f = __half22float2(h2[t]);
            s += f.x + f.y;
        }
    }
    #pragma unroll
    for (int o = 16; o; o >>= 1) s += __shfl_xor_sync(0xffffffffu, s, o);
    if (lane == 0) g_ksum[gw] = s;
}

// ---------------------------------------------------------------------------
// z[b,s] = 1 / (dot(q_phi[b,s,:], k_sum[b,:]) + 1e-6)
// ---------------------------------------------------------------------------
__global__ void z_k()
{
    const int gw = (blockIdx.x * blockDim.x + threadIdx.x) >> 5;  // 0..16383
    const int lane = threadIdx.x & 31;
    const int b = gw >> 12;
    const uint4* q4 = (const uint4*)(g_q16 + (size_t)gw * Dd);
    const float4* ks4 = (const float4*)(g_ksum + b * Dd);
    float s = 0.f;
    #pragma unroll
    for (int i = 0; i < 4; i++) {
        const int u = i * 32 + lane;
        uint4 xq = q4[u];
        float4 k0 = ks4[u * 2], k1 = ks4[u * 2 + 1];
        const __half2* h2 = (const __half2*)&xq;
        const float* kf = (const float*)&k0;
        #pragma unroll
        for (int t = 0; t < 2; t++) {
            float2 f = __half22float2(h2[t]);
            s += f.x * kf[t * 2] + f.y * kf[t * 2 + 1];
        }
        const float* kg = (const float*)&k1;
        #pragma unroll
        for (int t = 0; t < 2; t++) {
            float2 f = __half22float2(h2[2 + t]);
            s += f.x * kg[t * 2] + f.y * kg[t * 2 + 1];
        }
    }
    #pragma unroll
    for (int o = 16; o; o >>= 1) s += __shfl_xor_sync(0xffffffffu, s, o);
    if (lane == 0) g_z[gw] = 1.0f / (s + 1e-6f);
}

// ---------------------------------------------------------------------------
// Launch
// ---------------------------------------------------------------------------
extern "C" void kernel_launch(void* const* d_in, const int* in_sizes, int n_in,
                              void* d_out, int out_size)
{
    (void)in_sizes; (void)n_in; (void)out_size;
    const float* inputs  = (const float*)d_in[0];
    const float* context = (const float*)d_in[1];
    const float* Wq = (const float*)d_in[2];
    const float* bq = (const float*)d_in[3];
    const float* Wk = (const float*)d_in[4];
    const float* bk = (const float*)d_in[5];
    const float* Wv = (const float*)d_in[6];
    const float* bv = (const float*)d_in[7];
    const float* Wo = (const float*)d_in[8];
    const float* bo = (const float*)d_in[9];
    float* out = (float*)d_out;

    __half *i16, *c16, *q16, *kT, *vT, *at, *kvT, *Wt;
    float *zp;
    cudaGetSymbolAddress((void**)&i16, g_i16);
    cudaGetSymbolAddress((void**)&c16, g_c16);
    cudaGetSymbolAddress((void**)&q16, g_q16);
    cudaGetSymbolAddress((void**)&kT,  g_kT16);
    cudaGetSymbolAddress((void**)&vT,  g_vT16);
    cudaGetSymbolAddress((void**)&at,  g_at16);
    cudaGetSymbolAddress((void**)&kvT, g_kvT16);
    cudaGetSymbolAddress((void**)&Wt,  g_Wt16);
    cudaGetSymbolAddress((void**)&zp,  g_z);

    cudaFuncSetAttribute(mma_gemm<E_Q>,   cudaFuncAttributeMaxDynamicSharedMemorySize, SMEM_DYN);
    cudaFuncSetAttribute(mma_gemm<E_K>,   cudaFuncAttributeMaxDynamicSharedMemorySize, SMEM_DYN);
    cudaFuncSetAttribute(mma_gemm<E_V>,   cudaFuncAttributeMaxDynamicSharedMemorySize, SMEM_DYN);
    cudaFuncSetAttribute(mma_gemm<E_KVP>, cudaFuncAttributeMaxDynamicSharedMemorySize, SMEM_DYN);
    cudaFuncSetAttribute(mma_gemm<E_ATT>, cudaFuncAttributeMaxDynamicSharedMemorySize, SMEM_DYN);
    cudaFuncSetAttribute(mma_gemm<E_OUT>, cudaFuncAttributeMaxDynamicSharedMemorySize, SMEM_DYN);

    const size_t DD2 = (size_t)Dd * Dd;
    const dim3 blk(256);

    // 0. Convert weights (transposed) and activations to fp16
    wsplit_k<<<dim3(32, 32, 4), dim3(32, 8)>>>(Wq, Wk, Wv, Wo);
    tofp16_k<<<8192, 256>>>(inputs,  i16);
    tofp16_k<<<8192, 256>>>(context, c16);

    // 1-3. Projections (CTA tile 128x256: grid x = N/256 = 4)
    mma_gemm<E_Q><<<dim3(4, 128, 1), blk, SMEM_DYN>>>(
        i16, Wt, Dd, Dd, Dd, 0, 0, bq, nullptr, nullptr, nullptr, q16);
    mma_gemm<E_K><<<dim3(4, 128, 1), blk, SMEM_DYN>>>(
        c16, Wt + DD2, Dd, Dd, Dd, 0, 0, bk, nullptr, nullptr, nullptr, kT);
    mma_gemm<E_V><<<dim3(4, 128, 1), blk, SMEM_DYN>>>(
        c16, Wt + 2 * DD2, Dd, Dd, Dd, 0, 0, bv, nullptr, nullptr, nullptr, vT);

    // 4-5. k_sum, z
    ksum_k<<<512, 256>>>();
    z_k<<<2048, 256>>>();

    // 6. kv^T[b,e,d] = (k^T @ v)^T  (M=d rows, N=e cols, K=s)
    mma_gemm<E_KVP><<<dim3(4, 8, 4), blk, SMEM_DYN>>>(
        kT, vT, Ss, Ss, Ss,
        (long long)Dd * Ss, (long long)Dd * Ss,
        nullptr, nullptr, nullptr, nullptr, kvT);

    // 7. att[b,s,e] = (q_phi @ kv) * z * ATT_SCALE
    mma_gemm<E_ATT><<<dim3(4, 32, 4), blk, SMEM_DYN>>>(
        q16, kvT, Dd, Dd, Dd,
        (long long)Ss * Dd, (long long)Dd * Dd,
        nullptr, zp, nullptr, nullptr, at);

    // 8. out = (att_scaled @ Wo) / ATT_SCALE + bo + inputs
    mma_gemm<E_OUT><<<dim3(4, 128, 1), blk, SMEM_DYN>>>(
        at, Wt + 3 * DD2, Dd, Dd, Dd, 0, 0,
        bo, nullptr, inputs, out, nullptr);
}

// round 8
// speedup vs baseline: 1.2534x; 1.2534x over previous
#include <cuda_runtime.h>
#include <cuda_fp16.h>
#include <stdint.h>

#define Bb 4
#define Ss 4096
#define Dd 1024
#define MTOT (Bb * Ss)   // 16384

__device__ __half g_i16 [(size_t)MTOT * Dd];
__device__ __half g_c16 [(size_t)MTOT * Dd];
__device__ __half g_q16 [(size_t)MTOT * Dd];
__device__ __half g_kT16[(size_t)Bb * Dd * Ss];
__device__ __half g_vT16[(size_t)Bb * Dd * Ss];
__device__ __half g_at16[(size_t)MTOT * Dd];
__device__ __half g_kvT16[(size_t)Bb * Dd * Dd];
__device__ __half g_Wt16[(size_t)4 * Dd * Dd];
__device__ float  g_ksum[Bb * Dd];
__device__ float  g_z  [Bb * Ss];

#define ATT_SCALE    1024.0f
#define ATT_INVSCALE (1.0f / 1024.0f)

static __device__ __forceinline__ uint32_t smem_u32(const void* p) {
    uint32_t a;
    asm("{ .reg .u64 t; cvta.to.shared.u64 t, %1; cvt.u32.u64 %0, t; }"
        : "=r"(a) : "l"(p));
    return a;
}
static __device__ __forceinline__ void ldsm4(uint32_t* r, uint32_t addr) {
    asm volatile("ldmatrix.sync.aligned.m8n8.x4.shared.b16 {%0,%1,%2,%3}, [%4];"
                 : "=r"(r[0]), "=r"(r[1]), "=r"(r[2]), "=r"(r[3]) : "r"(addr));
}
static __device__ __forceinline__ void mma16816(float* d, const uint32_t* a,
                                                const uint32_t* b) {
    asm volatile(
        "mma.sync.aligned.m16n8k16.row.col.f32.f16.f16.f32 "
        "{%0,%1,%2,%3}, {%4,%5,%6,%7}, {%8,%9}, {%0,%1,%2,%3};"
        : "+f"(d[0]), "+f"(d[1]), "+f"(d[2]), "+f"(d[3])
        : "r"(a[0]), "r"(a[1]), "r"(a[2]), "r"(a[3]), "r"(b[0]), "r"(b[1]));
}
#define CP16(dst, src) \
    asm volatile("cp.async.cg.shared.global [%0], [%1], 16;" :: "r"(dst), "l"(src))
#define CP_COMMIT() asm volatile("cp.async.commit_group;" ::: "memory")
#define CP_WAIT1()  asm volatile("cp.async.wait_group 1;" ::: "memory")
static __device__ __forceinline__ uint32_t pack2h(__half a, __half b) {
    return (uint32_t)__half_as_ushort(a) | ((uint32_t)__half_as_ushort(b) << 16);
}

enum { E_Q = 0, E_KV = 1, E_KVP = 3, E_ATT = 4, E_OUT = 5 };

#define TILE_B   16384
#define STAGE_B  (2 * TILE_B)
#define SMEM_DYN (3 * STAGE_B)    // 98304

template<int EPI>
__global__ __launch_bounds__(128, 2)
void mma_gemm(const __half* __restrict__ Ag, const __half* __restrict__ Bg,
              int K, int lda, int ldb, long long sA, long long sB,
              const float* __restrict__ bias, const float* __restrict__ bias2,
              const float* __restrict__ zarr, const float* __restrict__ resid,
              float* __restrict__ Cf, __half* __restrict__ Ch,
              __half* __restrict__ Ch2)
{
    extern __shared__ __align__(1024) char dsm[];
    const uint32_t sbase = smem_u32(dsm);

    const int tid  = threadIdx.x;
    const int w    = tid >> 5, lane = tid & 31;
    const int wm0  = (w >> 1) * 64;
    const int wn0  = (w & 1) * 64;
    const int bz    = blockIdx.z;
    const int rbase = blockIdx.y * 128;
    const int cbase = blockIdx.x * 128;

    const __half* pA = Ag + (size_t)bz * sA;
    const __half* pB = Bg + (size_t)bz * sB;

    float acc[4][8][4];
    #pragma unroll
    for (int a = 0; a < 4; a++)
        #pragma unroll
        for (int b = 0; b < 8; b++)
            #pragma unroll
            for (int c = 0; c < 4; c++) acc[a][b][c] = 0.f;

    auto load_stage = [&](int stg, int it) {
        const uint32_t sb = sbase + stg * STAGE_B;
        const size_t k0 = (size_t)it * 64;
        #pragma unroll
        for (int i = 0; i < 8; i++) {
            const int row = (tid >> 3) + i * 16;
            const int u   = tid & 7;
            const uint32_t off = ((uint32_t)row << 7) + (uint32_t)((u ^ (row & 7)) << 4);
            const size_t ea = (size_t)(rbase + row) * lda + k0 + (size_t)u * 8;
            const size_t eb = (size_t)(cbase + row) * ldb + k0 + (size_t)u * 8;
            CP16(sb + off,          pA + ea);
            CP16(sb + TILE_B + off, pB + eb);
        }
    };

    const int nch = K >> 6;
    load_stage(0, 0); CP_COMMIT();
    load_stage(1, 1); CP_COMMIT();

    const int la15 = lane & 15, la7 = lane & 7;
    const uint32_t aRowB = (uint32_t)(wm0 + la15) << 7;
    const int aSel = lane >> 4;
    const int bRow = wn0 + la7 + ((lane >> 1) & 8);
    const int bSel = (lane >> 3) & 1;

    for (int it = 0; it < nch; ++it) {
        CP_WAIT1();
        __syncthreads();
        if (it + 2 < nch) load_stage((it + 2) % 3, it + 2);
        CP_COMMIT();

        const uint32_t sb = sbase + (it % 3) * STAGE_B;
        #pragma unroll
        for (int ks = 0; ks < 4; ++ks) {
            uint32_t ah[4][4], bh[4][4];
            #pragma unroll
            for (int mt = 0; mt < 4; mt++) {
                const uint32_t ad = sb + aRowB + (mt << 11)
                                  + (uint32_t)((((ks << 1) + aSel) ^ la7) << 4);
                ldsm4(ah[mt], ad);
            }
            #pragma unroll
            for (int nt = 0; nt < 4; nt++) {
                const uint32_t bd = sb + TILE_B
                                  + ((uint32_t)(bRow + (nt << 4)) << 7)
                                  + (uint32_t)((((ks << 1) + bSel) ^ la7) << 4);
                ldsm4(bh[nt], bd);
            }
            #pragma unroll
            for (int mt = 0; mt < 4; mt++)
                #pragma unroll
                for (int nt = 0; nt < 4; nt++)
                    #pragma unroll
                    for (int s2 = 0; s2 < 2; s2++)
                        mma16816(acc[mt][nt * 2 + s2], ah[mt], &bh[nt][s2 * 2]);
        }
    }

    const int rQ = lane >> 2;
    const int cP = (lane & 3) * 2;

    if (EPI == E_Q || EPI == E_ATT || EPI == E_OUT) {
        #pragma unroll
        for (int mt = 0; mt < 4; mt++)
            #pragma unroll
            for (int h = 0; h < 2; h++) {
                const int grow = rbase + wm0 + mt * 16 + rQ + h * 8;
                float zv = 1.f;
                if (EPI == E_ATT) zv = zarr[(size_t)bz * Ss + grow] * ATT_SCALE;
                #pragma unroll
                for (int nt8 = 0; nt8 < 8; nt8++) {
                    const int gcol = cbase + wn0 + nt8 * 8 + cP;
                    float v0 = acc[mt][nt8][h * 2 + 0];
                    float v1 = acc[mt][nt8][h * 2 + 1];
                    if (EPI == E_OUT) { v0 *= ATT_INVSCALE; v1 *= ATT_INVSCALE; }
                    if (EPI == E_Q || EPI == E_OUT) {
                        v0 += bias[gcol];
                        v1 += bias[gcol + 1];
                    }
                    if (EPI == E_Q) {
                        v0 = (v0 > 0.f) ? (v0 + 1.f) : __expf(v0);
                        v1 = (v1 > 0.f) ? (v1 + 1.f) : __expf(v1);
                    }
                    if (EPI == E_ATT) { v0 *= zv; v1 *= zv; }
                    if (EPI == E_OUT) {
                        const size_t gi = (size_t)grow * Dd + gcol;
                        float2 rv = *(const float2*)(resid + gi);
                        *(float2*)(Cf + gi) = make_float2(v0 + rv.x, v1 + rv.y);
                    } else {
                        const size_t gi = (EPI == E_Q)
                            ? (size_t)grow * Dd + gcol
                            : ((size_t)bz * Ss + grow) * (size_t)Dd + gcol;
                        *(uint32_t*)(Ch + gi) =
                            pack2h(__float2half_rn(v0), __float2half_rn(v1));
                    }
                }
            }
    } else {
        // E_KV (fused K|V projection) and E_KVP: smem transpose staging
        const int sec = (EPI == E_KV) ? (cbase >> 10) : 0;   // 0=K(phi), 1=V
        const int cm  = (EPI == E_KV) ? (cbase & 1023) : cbase;
        const float* bp = (EPI == E_KV) ? (sec ? bias2 : bias) : bias;
        __syncthreads();
        __half* sT = (__half*)dsm;
        #pragma unroll
        for (int mt = 0; mt < 4; mt++)
            #pragma unroll
            for (int h = 0; h < 2; h++) {
                const int r = wm0 + mt * 16 + rQ + h * 8;
                #pragma unroll
                for (int nt8 = 0; nt8 < 8; nt8++) {
                    const int c = wn0 + nt8 * 8 + cP;
                    float v0 = acc[mt][nt8][h * 2 + 0];
                    float v1 = acc[mt][nt8][h * 2 + 1];
                    if (EPI == E_KV) {
                        v0 += bp[cm + c];
                        v1 += bp[cm + c + 1];
                        if (sec == 0) {
                            v0 = (v0 > 0.f) ? (v0 + 1.f) : __expf(v0);
                            v1 = (v1 > 0.f) ? (v1 + 1.f) : __expf(v1);
                        }
                    }
                    sT[c * 136 + r]       = __float2half_rn(v0);
                    sT[(c + 1) * 136 + r] = __float2half_rn(v1);
                }
            }
        __syncthreads();
        const int bGl = rbase >> 12;
        const int s0  = rbase & (Ss - 1);
        __half* dst = (EPI == E_KV && sec == 1) ? Ch2 : Ch;
        #pragma unroll
        for (int i = 0; i < 16; i++) {
            const int e  = i * 128 + tid;
            const int c  = e >> 4;
            const int ru = e & 15;
            uint4 hv = *(const uint4*)(sT + c * 136 + ru * 8);
            size_t gi;
            if (EPI == E_KVP)
                gi = ((size_t)bz * Dd + cbase + c) * (size_t)Dd + rbase + ru * 8;
            else
                gi = ((size_t)bGl * Dd + cm + c) * (size_t)Ss + s0 + ru * 8;
            *(uint4*)(dst + gi) = hv;
        }
    }
}

__global__ void tofp16_k(const float* __restrict__ x0, const float* __restrict__ x1)
{
    const float* x = blockIdx.y ? x1 : x0;
    __half* h = blockIdx.y ? g_c16 : g_i16;
    const size_t i = ((size_t)blockIdx.x * 256 + threadIdx.x) * 8;
    float4 a = *(const float4*)(x + i);
    float4 b = *(const float4*)(x + i + 4);
    uint4 o;
    o.x = pack2h(__float2half_rn(a.x), __float2half_rn(a.y));
    o.y = pack2h(__float2half_rn(a.z), __float2half_rn(a.w));
    o.z = pack2h(__float2half_rn(b.x), __float2half_rn(b.y));
    o.w = pack2h(__float2half_rn(b.z), __float2half_rn(b.w));
    *(uint4*)(h + i) = o;
}

__global__ void wsplit_k(const float* __restrict__ Wq, const float* __restrict__ Wk,
                         const float* __restrict__ Wv, const float* __restrict__ Wo)
{
    __shared__ float t[32][33];
    const float* W = (blockIdx.z == 0) ? Wq : (blockIdx.z == 1) ? Wk
                   : (blockIdx.z == 2) ? Wv : Wo;
    __half* Th = g_Wt16 + (size_t)blockIdx.z * Dd * Dd;
    const int n0 = blockIdx.x * 32, k0 = blockIdx.y * 32;
    const int tx = threadIdx.x, ty = threadIdx.y;
    #pragma unroll
    for (int i = 0; i < 4; i++)
        t[ty + i * 8][tx] = W[(size_t)(k0 + ty + i * 8) * Dd + n0 + tx];
    __syncthreads();
    #pragma unroll
    for (int i = 0; i < 4; i++) {
        const int r = ty + i * 8;
        Th[(size_t)(n0 + r) * Dd + k0 + tx] = __float2half_rn(t[tx][r]);
    }
}

__global__ void ksum_k()
{
    const int gw = (blockIdx.x * blockDim.x + threadIdx.x) >> 5;
    const int lane = threadIdx.x & 31;
    const uint4* ph = (const uint4*)(g_kT16 + (size_t)gw * Ss);
    float s = 0.f;
    #pragma unroll 4
    for (int i = 0; i < 16; i++) {
        uint4 xh = ph[i * 32 + lane];
        const __half2* h2 = (const __half2*)&xh;
        #pragma unroll
        for (int t = 0; t < 4; t++) {
            float2 f = __half22float2(h2[t]);
            s += f.x + f.y;
        }
    }
    #pragma unroll
    for (int o = 16; o; o >>= 1) s += __shfl_xor_sync(0xffffffffu, s, o);
    if (lane == 0) g_ksum[gw] = s;
}

__global__ void z_k()
{
    const int gw = (blockIdx.x * blockDim.x + threadIdx.x) >> 5;
    const int lane = threadIdx.x & 31;
    const int b = gw >> 12;
    const uint4* q4 = (const uint4*)(g_q16 + (size_t)gw * Dd);
    const float4* ks4 = (const float4*)(g_ksum + b * Dd);
    float s = 0.f;
    #pragma unroll
    for (int i = 0; i < 4; i++) {
        const int u = i * 32 + lane;
        uint4 xq = q4[u];
        float4 k0 = ks4[u * 2], k1 = ks4[u * 2 + 1];
        const __half2* h2 = (const __half2*)&xq;
        const float* kf = (const float*)&k0;
        #pragma unroll
        for (int t = 0; t < 2; t++) {
            float2 f = __half22float2(h2[t]);
            s += f.x * kf[t * 2] + f.y * kf[t * 2 + 1];
        }
        const float* kg = (const float*)&k1;
        #pragma unroll
        for (int t = 0; t < 2; t++) {
            float2 f = __half22float2(h2[2 + t]);
            s += f.x * kg[t * 2] + f.y * kg[t * 2 + 1];
        }
    }
    #pragma unroll
    for (int o = 16; o; o >>= 1) s += __shfl_xor_sync(0xffffffffu, s, o);
    if (lane == 0) g_z[gw] = 1.0f / (s + 1e-6f);
}

extern "C" void kernel_launch(void* const* d_in, const int* in_sizes, int n_in,
                              void* d_out, int out_size)
{
    (void)in_sizes; (void)n_in; (void)out_size;
    const float* inputs  = (const float*)d_in[0];
    const float* context = (const float*)d_in[1];
    const float* Wq = (const float*)d_in[2];
    const float* bq = (const float*)d_in[3];
    const float* Wk = (const float*)d_in[4];
    const float* bk = (const float*)d_in[5];
    const float* Wv = (const float*)d_in[6];
    const float* bv = (const float*)d_in[7];
    const float* Wo = (const float*)d_in[8];
    const float* bo = (const float*)d_in[9];
    float* out = (float*)d_out;

    __half *i16, *c16, *q16, *kT, *vT, *at, *kvT, *Wt;
    float *zp;
    cudaGetSymbolAddress((void**)&i16, g_i16);
    cudaGetSymbolAddress((void**)&c16, g_c16);
    cudaGetSymbolAddress((void**)&q16, g_q16);
    cudaGetSymbolAddress((void**)&kT,  g_kT16);
    cudaGetSymbolAddress((void**)&vT,  g_vT16);
    cudaGetSymbolAddress((void**)&at,  g_at16);
    cudaGetSymbolAddress((void**)&kvT, g_kvT16);
    cudaGetSymbolAddress((void**)&Wt,  g_Wt16);
    cudaGetSymbolAddress((void**)&zp,  g_z);

    cudaFuncSetAttribute(mma_gemm<E_Q>,   cudaFuncAttributeMaxDynamicSharedMemorySize, SMEM_DYN);
    cudaFuncSetAttribute(mma_gemm<E_KV>,  cudaFuncAttributeMaxDynamicSharedMemorySize, SMEM_DYN);
    cudaFuncSetAttribute(mma_gemm<E_KVP>, cudaFuncAttributeMaxDynamicSharedMemorySize, SMEM_DYN);
    cudaFuncSetAttribute(mma_gemm<E_ATT>, cudaFuncAttributeMaxDynamicSharedMemorySize, SMEM_DYN);
    cudaFuncSetAttribute(mma_gemm<E_OUT>, cudaFuncAttributeMaxDynamicSharedMemorySize, SMEM_DYN);

    const size_t DD2 = (size_t)Dd * Dd;
    const dim3 blk(128);

    wsplit_k<<<dim3(32, 32, 4), dim3(32, 8)>>>(Wq, Wk, Wv, Wo);
    tofp16_k<<<dim3(8192, 2), 256>>>(inputs, context);

    // 1. Q projection — grid 1024
    mma_gemm<E_Q><<<dim3(8, 128, 1), blk, SMEM_DYN>>>(
        i16, Wt, Dd, Dd, Dd, 0, 0, bq, nullptr, nullptr, nullptr, nullptr,
        q16, nullptr);

    // 2. Fused K|V projection — grid 2048 (N=2048 over Wk^T|Wv^T contiguous)
    mma_gemm<E_KV><<<dim3(16, 128, 1), blk, SMEM_DYN>>>(
        c16, Wt + DD2, Dd, Dd, Dd, 0, 0, bk, bv, nullptr, nullptr, nullptr,
        kT, vT);

    ksum_k<<<512, 256>>>();
    z_k<<<2048, 256>>>();

    // 3. kv^T — grid 256 (single wave at 2 CTAs/SM)
    mma_gemm<E_KVP><<<dim3(8, 8, 4), blk, SMEM_DYN>>>(
        kT, vT, Ss, Ss, Ss,
        (long long)Dd * Ss, (long long)Dd * Ss,
        nullptr, nullptr, nullptr, nullptr, nullptr, kvT, nullptr);

    // 4. att = (q_phi @ kv) * z * ATT_SCALE
    mma_gemm<E_ATT><<<dim3(8, 32, 4), blk, SMEM_DYN>>>(
        q16, kvT, Dd, Dd, Dd,
        (long long)Ss * Dd, (long long)Dd * Dd,
        nullptr, nullptr, zp, nullptr, nullptr, at, nullptr);

    // 5. out = (att_scaled @ Wo) / ATT_SCALE + bo + inputs
    mma_gemm<E_OUT><<<dim3(8, 128, 1), blk, SMEM_DYN>>>(
        at, Wt + 3 * DD2, Dd, Dd, Dd, 0, 0,
        bo, nullptr, nullptr, inputs, out, nullptr, nullptr);
}

// round 10
// speedup vs baseline: 1.2696x; 1.0129x over previous
#include <cuda_runtime.h>
#include <cuda_fp16.h>
#include <stdint.h>

#define Bb 4
#define Ss 4096
#define Dd 1024
#define MTOT (Bb * Ss)   // 16384

__device__ __half g_i16 [(size_t)MTOT * Dd];
__device__ __half g_c16 [(size_t)MTOT * Dd];
__device__ __half g_q16 [(size_t)MTOT * Dd];
__device__ __half g_kT16[(size_t)Bb * Dd * Ss];
__device__ __half g_vT16[(size_t)Bb * Dd * Ss];
__device__ __half g_at16[(size_t)MTOT * Dd];
__device__ __half g_kvT16[(size_t)Bb * Dd * Dd];
__device__ __half g_Wt16[(size_t)4 * Dd * Dd];   // Wq^T|Wk^T|Wv^T|Wo^T
__device__ float  g_ksum[Bb * Dd];
__device__ float  g_z  [Bb * Ss];

#define ATT_SCALE    1024.0f
#define ATT_INVSCALE (1.0f / 1024.0f)

static __device__ __forceinline__ uint32_t smem_u32(const void* p) {
    uint32_t a;
    asm("{ .reg .u64 t; cvta.to.shared.u64 t, %1; cvt.u32.u64 %0, t; }"
        : "=r"(a) : "l"(p));
    return a;
}
static __device__ __forceinline__ void ldsm4(uint32_t* r, uint32_t addr) {
    asm volatile("ldmatrix.sync.aligned.m8n8.x4.shared.b16 {%0,%1,%2,%3}, [%4];"
                 : "=r"(r[0]), "=r"(r[1]), "=r"(r[2]), "=r"(r[3]) : "r"(addr));
}
static __device__ __forceinline__ void mma16816(float* d, const uint32_t* a,
                                                const uint32_t* b) {
    asm volatile(
        "mma.sync.aligned.m16n8k16.row.col.f32.f16.f16.f32 "
        "{%0,%1,%2,%3}, {%4,%5,%6,%7}, {%8,%9}, {%0,%1,%2,%3};"
        : "+f"(d[0]), "+f"(d[1]), "+f"(d[2]), "+f"(d[3])
        : "r"(a[0]), "r"(a[1]), "r"(a[2]), "r"(a[3]), "r"(b[0]), "r"(b[1]));
}
#define CP16(dst, src) \
    asm volatile("cp.async.cg.shared.global [%0], [%1], 16;" :: "r"(dst), "l"(src))
#define CP_COMMIT() asm volatile("cp.async.commit_group;" ::: "memory")
#define CP_WAIT1()  asm volatile("cp.async.wait_group 1;" ::: "memory")
static __device__ __forceinline__ uint32_t pack2h(__half a, __half b) {
    return (uint32_t)__half_as_ushort(a) | ((uint32_t)__half_as_ushort(b) << 16);
}

// EPI kinds:
//  E_PROJ: fused QKV projection. N=3072. sec = cbase>>10: 0=Q(phi,direct),
//          1=K(phi,transpose,+ksum atomics), 2=V(transpose).
//          A = sec==0 ? Ag : Ag2.
//  E_KVP : kv^T batched GEMM (transpose epilogue, no bias)
//  E_ATT : (q @ kv) * z * ATT_SCALE, direct fp16 store
//  E_OUT : att @ Wo^T * INV + bias + residual, fp32 store
enum { E_PROJ = 0, E_KVP = 3, E_ATT = 4, E_OUT = 5 };

#define TILE_B   16384
#define STAGE_B  (2 * TILE_B)
#define SMEM_DYN (3 * STAGE_B)    // 98304

template<int EPI>
__global__ __launch_bounds__(128, 2)
void mma_gemm(const __half* __restrict__ Ag, const __half* __restrict__ Ag2,
              const __half* __restrict__ Bg,
              int K, int lda, int ldb, long long sA, long long sB,
              const float* __restrict__ b0, const float* __restrict__ b1,
              const float* __restrict__ b2,
              const float* __restrict__ zarr, const float* __restrict__ resid,
              float* __restrict__ Cf, __half* __restrict__ Ch,
              __half* __restrict__ Ch2, __half* __restrict__ Ch3)
{
    extern __shared__ __align__(1024) char dsm[];
    const uint32_t sbase = smem_u32(dsm);

    const int tid  = threadIdx.x;
    const int w    = tid >> 5, lane = tid & 31;
    const int wm0  = (w >> 1) * 64;
    const int wn0  = (w & 1) * 64;
    const int bz    = blockIdx.z;
    const int rbase = blockIdx.y * 128;
    const int cbase = blockIdx.x * 128;
    const int sec   = (EPI == E_PROJ) ? (cbase >> 10) : 0;
    const int cm    = (EPI == E_PROJ) ? (cbase & 1023) : cbase;

    const __half* pAsel = (EPI == E_PROJ && sec != 0) ? Ag2 : Ag;
    const __half* pA = pAsel + (size_t)bz * sA;
    const __half* pB = Bg + (size_t)bz * sB;

    float acc[4][8][4];
    #pragma unroll
    for (int a = 0; a < 4; a++)
        #pragma unroll
        for (int b = 0; b < 8; b++)
            #pragma unroll
            for (int c = 0; c < 4; c++) acc[a][b][c] = 0.f;

    auto load_stage = [&](int stg, int it) {
        const uint32_t sb = sbase + stg * STAGE_B;
        const size_t k0 = (size_t)it * 64;
        #pragma unroll
        for (int i = 0; i < 8; i++) {
            const int row = (tid >> 3) + i * 16;
            const int u   = tid & 7;
            const uint32_t off = ((uint32_t)row << 7) + (uint32_t)((u ^ (row & 7)) << 4);
            const size_t ea = (size_t)(rbase + row) * lda + k0 + (size_t)u * 8;
            const size_t eb = (size_t)(cbase + row) * ldb + k0 + (size_t)u * 8;
            CP16(sb + off,          pA + ea);
            CP16(sb + TILE_B + off, pB + eb);
        }
    };

    const int nch = K >> 6;
    load_stage(0, 0); CP_COMMIT();
    load_stage(1, 1); CP_COMMIT();

    const int la15 = lane & 15, la7 = lane & 7;
    const uint32_t aRowB = (uint32_t)(wm0 + la15) << 7;
    const int aSel = lane >> 4;
    const int bRow = wn0 + la7 + ((lane >> 1) & 8);
    const int bSel = (lane >> 3) & 1;

    for (int it = 0; it < nch; ++it) {
        CP_WAIT1();
        __syncthreads();
        if (it + 2 < nch) load_stage((it + 2) % 3, it + 2);
        CP_COMMIT();

        const uint32_t sb = sbase + (it % 3) * STAGE_B;
        #pragma unroll
        for (int ks = 0; ks < 4; ++ks) {
            uint32_t ah[4][4], bh[4][4];
            #pragma unroll
            for (int mt = 0; mt < 4; mt++) {
                const uint32_t ad = sb + aRowB + (mt << 11)
                                  + (uint32_t)((((ks << 1) + aSel) ^ la7) << 4);
                ldsm4(ah[mt], ad);
            }
            #pragma unroll
            for (int nt = 0; nt < 4; nt++) {
                const uint32_t bd = sb + TILE_B
                                  + ((uint32_t)(bRow + (nt << 4)) << 7)
                                  + (uint32_t)((((ks << 1) + bSel) ^ la7) << 4);
                ldsm4(bh[nt], bd);
            }
            #pragma unroll
            for (int mt = 0; mt < 4; mt++)
                #pragma unroll
                for (int nt = 0; nt < 4; nt++)
                    #pragma unroll
                    for (int s2 = 0; s2 < 2; s2++)
                        mma16816(acc[mt][nt * 2 + s2], ah[mt], &bh[nt][s2 * 2]);
        }
    }

    const int rQ = lane >> 2;
    const int cP = (lane & 3) * 2;

    const bool direct = (EPI == E_ATT || EPI == E_OUT ||
                         (EPI == E_PROJ && sec == 0));

    if (direct) {
        const float* bp = b0;   // Q bias (E_PROJ sec0) / out bias (E_OUT)
        #pragma unroll
        for (int mt = 0; mt < 4; mt++)
            #pragma unroll
            for (int h = 0; h < 2; h++) {
                const int grow = rbase + wm0 + mt * 16 + rQ + h * 8;
                float zv = 1.f;
                if (EPI == E_ATT) zv = zarr[(size_t)bz * Ss + grow] * ATT_SCALE;
                #pragma unroll
                for (int nt8 = 0; nt8 < 8; nt8++) {
                    const int col = wn0 + nt8 * 8 + cP;
                    float v0 = acc[mt][nt8][h * 2 + 0];
                    float v1 = acc[mt][nt8][h * 2 + 1];
                    if (EPI == E_OUT) { v0 *= ATT_INVSCALE; v1 *= ATT_INVSCALE; }
                    if (EPI == E_PROJ || EPI == E_OUT) {
                        v0 += bp[cm + col];
                        v1 += bp[cm + col + 1];
                    }
                    if (EPI == E_PROJ) {   // Q section: phi
                        v0 = (v0 > 0.f) ? (v0 + 1.f) : __expf(v0);
                        v1 = (v1 > 0.f) ? (v1 + 1.f) : __expf(v1);
                    }
                    if (EPI == E_ATT) { v0 *= zv; v1 *= zv; }
                    if (EPI == E_OUT) {
                        const size_t gi = (size_t)grow * Dd + cm + col;
                        float2 rv = *(const float2*)(resid + gi);
                        *(float2*)(Cf + gi) = make_float2(v0 + rv.x, v1 + rv.y);
                    } else {
                        const size_t gi = (EPI == E_PROJ)
                            ? (size_t)grow * Dd + cm + col
                            : ((size_t)bz * Ss + grow) * (size_t)Dd + cm + col;
                        *(uint32_t*)(Ch + gi) =
                            pack2h(__float2half_rn(v0), __float2half_rn(v1));
                    }
                }
            }
    } else {
        // transpose epilogue: E_PROJ sec 1 (K, phi, +ksum) / sec 2 (V), E_KVP
        const float* bp = (EPI == E_PROJ) ? (sec == 1 ? b1 : b2) : nullptr;
        __syncthreads();
        __half* sT = (__half*)dsm;
        #pragma unroll
        for (int mt = 0; mt < 4; mt++)
            #pragma unroll
            for (int h = 0; h < 2; h++) {
                const int r = wm0 + mt * 16 + rQ + h * 8;
                #pragma unroll
                for (int nt8 = 0; nt8 < 8; nt8++) {
                    const int c = wn0 + nt8 * 8 + cP;
                    float v0 = acc[mt][nt8][h * 2 + 0];
                    float v1 = acc[mt][nt8][h * 2 + 1];
                    if (EPI == E_PROJ) {
                        v0 += bp[cm + c];
                        v1 += bp[cm + c + 1];
                        if (sec == 1) {
                            v0 = (v0 > 0.f) ? (v0 + 1.f) : __expf(v0);
                            v1 = (v1 > 0.f) ? (v1 + 1.f) : __expf(v1);
                        }
                    }
                    sT[c * 136 + r]       = __float2half_rn(v0);
                    sT[(c + 1) * 136 + r] = __float2half_rn(v1);
                }
            }
        __syncthreads();
        const int bGl = rbase >> 12;
        const int s0  = rbase & (Ss - 1);
        __half* dst = (EPI == E_PROJ) ? (sec == 1 ? Ch2 : Ch3) : Ch;
        #pragma unroll
        for (int i = 0; i < 16; i++) {
            const int e  = i * 128 + tid;
            const int c  = e >> 4;
            const int ru = e & 15;
            uint4 hv = *(const uint4*)(sT + c * 136 + ru * 8);
            size_t gi;
            if (EPI == E_KVP)
                gi = ((size_t)bz * Dd + cbase + c) * (size_t)Dd + rbase + ru * 8;
            else
                gi = ((size_t)bGl * Dd + cm + c) * (size_t)Ss + s0 + ru * 8;
            *(uint4*)(dst + gi) = hv;
            if (EPI == E_PROJ && sec == 1) {
                // fold k_sum: this thread holds 8 consecutive s-values of
                // column (bGl, cm+c) — reduce and atomically accumulate.
                const __half2* h2 = (const __half2*)&hv;
                float ssum = 0.f;
                #pragma unroll
                for (int t = 0; t < 4; t++) {
                    float2 f = __half22float2(h2[t]);
                    ssum += f.x + f.y;
                }
                atomicAdd(&g_ksum[bGl * Dd + cm + c], ssum);
            }
        }
    }
}

// ---------------------------------------------------------------------------
// fp32 -> fp16 convert; y=0 -> inputs (block 0 also zeroes g_ksum), y=1 -> ctx
// ---------------------------------------------------------------------------
__global__ void tofp16_k(const float* __restrict__ x0, const float* __restrict__ x1)
{
    if (blockIdx.y == 0 && blockIdx.x == 0) {
        #pragma unroll
        for (int i = 0; i < (Bb * Dd) / 256; i++)
            g_ksum[i * 256 + threadIdx.x] = 0.f;
    }
    const float* x = blockIdx.y ? x1 : x0;
    __half* h = blockIdx.y ? g_c16 : g_i16;
    const size_t i = ((size_t)blockIdx.x * 256 + threadIdx.x) * 8;
    float4 a = *(const float4*)(x + i);
    float4 b = *(const float4*)(x + i + 4);
    uint4 o;
    o.x = pack2h(__float2half_rn(a.x), __float2half_rn(a.y));
    o.y = pack2h(__float2half_rn(a.z), __float2half_rn(a.w));
    o.z = pack2h(__float2half_rn(b.x), __float2half_rn(b.y));
    o.w = pack2h(__float2half_rn(b.z), __float2half_rn(b.w));
    *(uint4*)(h + i) = o;
}

__global__ void wsplit_k(const float* __restrict__ Wq, const float* __restrict__ Wk,
                         const float* __restrict__ Wv, const float* __restrict__ Wo)
{
    __shared__ float t[32][33];
    const float* W = (blockIdx.z == 0) ? Wq : (blockIdx.z == 1) ? Wk
                   : (blockIdx.z == 2) ? Wv : Wo;
    __half* Th = g_Wt16 + (size_t)blockIdx.z * Dd * Dd;
    const int n0 = blockIdx.x * 32, k0 = blockIdx.y * 32;
    const int tx = threadIdx.x, ty = threadIdx.y;
    #pragma unroll
    for (int i = 0; i < 4; i++)
        t[ty + i * 8][tx] = W[(size_t)(k0 + ty + i * 8) * Dd + n0 + tx];
    __syncthreads();
    #pragma unroll
    for (int i = 0; i < 4; i++) {
        const int r = ty + i * 8;
        Th[(size_t)(n0 + r) * Dd + k0 + tx] = __float2half_rn(t[tx][r]);
    }
}

__global__ void z_k()
{
    const int gw = (blockIdx.x * blockDim.x + threadIdx.x) >> 5;
    const int lane = threadIdx.x & 31;
    const int b = gw >> 12;
    const uint4* q4 = (const uint4*)(g_q16 + (size_t)gw * Dd);
    const float4* ks4 = (const float4*)(g_ksum + b * Dd);
    float s = 0.f;
    #pragma unroll
    for (int i = 0; i < 4; i++) {
        const int u = i * 32 + lane;
        uint4 xq = q4[u];
        float4 k0 = ks4[u * 2], k1 = ks4[u * 2 + 1];
        const __half2* h2 = (const __half2*)&xq;
        const float* kf = (const float*)&k0;
        #pragma unroll
        for (int t = 0; t < 2; t++) {
            float2 f = __half22float2(h2[t]);
            s += f.x * kf[t * 2] + f.y * kf[t * 2 + 1];
        }
        const float* kg = (const float*)&k1;
        #pragma unroll
        for (int t = 0; t < 2; t++) {
            float2 f = __half22float2(h2[2 + t]);
            s += f.x * kg[t * 2] + f.y * kg[t * 2 + 1];
        }
    }
    #pragma unroll
    for (int o = 16; o; o >>= 1) s += __shfl_xor_sync(0xffffffffu, s, o);
    if (lane == 0) g_z[gw] = 1.0f / (s + 1e-6f);
}

extern "C" void kernel_launch(void* const* d_in, const int* in_sizes, int n_in,
                              void* d_out, int out_size)
{
    (void)in_sizes; (void)n_in; (void)out_size;
    const float* inputs  = (const float*)d_in[0];
    const float* context = (const float*)d_in[1];
    const float* Wq = (const float*)d_in[2];
    const float* bq = (const float*)d_in[3];
    const float* Wk = (const float*)d_in[4];
    const float* bk = (const float*)d_in[5];
    const float* Wv = (const float*)d_in[6];
    const float* bv = (const float*)d_in[7];
    const float* Wo = (const float*)d_in[8];
    const float* bo = (const float*)d_in[9];
    float* out = (float*)d_out;

    __half *i16, *c16, *q16, *kT, *vT, *at, *kvT, *Wt;
    float *zp;
    cudaGetSymbolAddress((void**)&i16, g_i16);
    cudaGetSymbolAddress((void**)&c16, g_c16);
    cudaGetSymbolAddress((void**)&q16, g_q16);
    cudaGetSymbolAddress((void**)&kT,  g_kT16);
    cudaGetSymbolAddress((void**)&vT,  g_vT16);
    cudaGetSymbolAddress((void**)&at,  g_at16);
    cudaGetSymbolAddress((void**)&kvT, g_kvT16);
    cudaGetSymbolAddress((void**)&Wt,  g_Wt16);
    cudaGetSymbolAddress((void**)&zp,  g_z);

    cudaFuncSetAttribute(mma_gemm<E_PROJ>, cudaFuncAttributeMaxDynamicSharedMemorySize, SMEM_DYN);
    cudaFuncSetAttribute(mma_gemm<E_KVP>,  cudaFuncAttributeMaxDynamicSharedMemorySize, SMEM_DYN);
    cudaFuncSetAttribute(mma_gemm<E_ATT>,  cudaFuncAttributeMaxDynamicSharedMemorySize, SMEM_DYN);
    cudaFuncSetAttribute(mma_gemm<E_OUT>,  cudaFuncAttributeMaxDynamicSharedMemorySize, SMEM_DYN);

    const size_t DD2 = (size_t)Dd * Dd;
    const dim3 blk(128);

    // 0. Weight transpose; activation conversion (+ g_ksum zeroing)
    wsplit_k<<<dim3(32, 32, 4), dim3(32, 8)>>>(Wq, Wk, Wv, Wo);
    tofp16_k<<<dim3(8192, 2), 256>>>(inputs, context);

    // 1. Fused QKV projection — N=3072 over Wq^T|Wk^T|Wv^T, grid 24x128.
    //    sec0: Q(phi)->q16 direct; sec1: K(phi)->kT transpose (+k_sum);
    //    sec2: V->vT transpose.
    mma_gemm<E_PROJ><<<dim3(24, 128, 1), blk, SMEM_DYN>>>(
        i16, c16, Wt, Dd, Dd, Dd, 0, 0, bq, bk, bv,
        nullptr, nullptr, nullptr, q16, kT, vT);

    // 2. z (k_sum already accumulated by projection epilogue)
    z_k<<<2048, 256>>>();

    // 3. kv^T — grid 256 (single wave at 2 CTAs/SM)
    mma_gemm<E_KVP><<<dim3(8, 8, 4), blk, SMEM_DYN>>>(
        kT, nullptr, vT, Ss, Ss, Ss,
        (long long)Dd * Ss, (long long)Dd * Ss,
        nullptr, nullptr, nullptr, nullptr, nullptr, nullptr, kvT, nullptr, nullptr);

    // 4. att = (q_phi @ kv) * z * ATT_SCALE
    mma_gemm<E_ATT><<<dim3(8, 32, 4), blk, SMEM_DYN>>>(
        q16, nullptr, kvT, Dd, Dd, Dd,
        (long long)Ss * Dd, (long long)Dd * Dd,
        nullptr, nullptr, nullptr, zp, nullptr, nullptr, at, nullptr, nullptr);

    // 5. out = (att_scaled @ Wo^T) / ATT_SCALE + bo + inputs
    mma_gemm<E_OUT><<<dim3(8, 128, 1), blk, SMEM_DYN>>>(
        at, nullptr, Wt + 3 * DD2, Dd, Dd, Dd, 0, 0,
        bo, nullptr, nullptr, nullptr, inputs, out, nullptr, nullptr, nullptr);
}